// round 17
// baseline (speedup 1.0000x reference)
#include <cuda_runtime.h>
#include <cuda_fp16.h>
#include <stdint.h>
#include <math.h>

#define Bc   4
#define C    48
#define C3   144
#define HH   256
#define WW   256
#define NPIX 65536   // HH*WW

typedef unsigned long long u64;
typedef unsigned int u32;

__device__ __forceinline__ u32 smem_u32(const void* p) {
    return (u32)__cvta_generic_to_shared(p);
}

// ---- scratch (device globals: no allocation allowed) ----
__device__ __half g_qkv[(size_t)Bc * C3 * NPIX];
__device__ __half g_dw [(size_t)Bc * C3 * NPIX];
__device__ float  g_small[Bc * (C * C + 2 * C)];
__device__ float  g_M[Bc * C * C];
__device__ int    g_cnt[Bc];

// ============================================================
// K1: qkv 1x1 conv via mma.m16n8k16, 256 px/block, x4.trans B.
// Xs pitch 264 half = 528B = 33*16B (odd) -> conflict-free ldmatrix.
// ============================================================
__global__ void __launch_bounds__(288) k_qkv(const float* __restrict__ x,
                                             const float* __restrict__ w) {
    __shared__ __half Ws[C3][56];    // 16.1 KB
    __shared__ __half Xs[C][264];    // 24.8 KB
    const int tid  = threadIdx.x;
    const int warp = tid >> 5, lane = tid & 31;
    const int b    = blockIdx.x >> 8;            // 256 blocks / batch
    const int px0  = (blockIdx.x & 255) << 8;    // 256 px / block

    for (int i = tid; i < C3 * C; i += 288) {
        int m = i / C, k = i % C;
        Ws[m][k] = __float2half_rn(w[i]);
    }
    const float* xb = x + (size_t)b * C * NPIX + px0;
    for (int i = tid; i < C * 64; i += 288) {
        int k = i >> 6, q = i & 63;
        float4 v = *(const float4*)(xb + (size_t)k * NPIX + (q << 2));
        *(__half2*)&Xs[k][q * 4]     = __floats2half2_rn(v.x, v.y);
        *(__half2*)&Xs[k][q * 4 + 2] = __floats2half2_rn(v.z, v.w);
    }
    __syncthreads();

    const int m0 = warp * 16;
    u32 a[3][4];
#pragma unroll
    for (int ks = 0; ks < 3; ks++) {
        u32 addr = smem_u32(&Ws[m0 + (lane & 15)][(lane >> 4) * 8 + ks * 16]);
        asm volatile("ldmatrix.sync.aligned.m8n8.x4.shared.b16 {%0,%1,%2,%3}, [%4];"
                     : "=r"(a[ks][0]), "=r"(a[ks][1]), "=r"(a[ks][2]), "=r"(a[ks][3])
                     : "r"(addr));
    }

    __half* ob = g_qkv + (size_t)b * C3 * NPIX + px0;
    const int g = lane >> 2, t = lane & 3;
#pragma unroll 2
    for (int n = 0; n < 32; n += 2) {
        float c0[4] = {0.f, 0.f, 0.f, 0.f};
        float c1[4] = {0.f, 0.f, 0.f, 0.f};
#pragma unroll
        for (int ks = 0; ks < 3; ks++) {
            u32 b0, b1, b2, b3;
            u32 baddr = smem_u32(&Xs[ks * 16 + (lane & 15)][(n + (lane >> 4)) * 8]);
            asm volatile("ldmatrix.sync.aligned.m8n8.x4.trans.shared.b16 {%0,%1,%2,%3}, [%4];"
                         : "=r"(b0), "=r"(b1), "=r"(b2), "=r"(b3) : "r"(baddr));
            asm volatile("mma.sync.aligned.m16n8k16.row.col.f32.f16.f16.f32 "
                         "{%0,%1,%2,%3}, {%4,%5,%6,%7}, {%8,%9}, {%0,%1,%2,%3};"
                         : "+f"(c0[0]), "+f"(c0[1]), "+f"(c0[2]), "+f"(c0[3])
                         : "r"(a[ks][0]), "r"(a[ks][1]), "r"(a[ks][2]), "r"(a[ks][3]),
                           "r"(b0), "r"(b1));
            asm volatile("mma.sync.aligned.m16n8k16.row.col.f32.f16.f16.f32 "
                         "{%0,%1,%2,%3}, {%4,%5,%6,%7}, {%8,%9}, {%0,%1,%2,%3};"
                         : "+f"(c1[0]), "+f"(c1[1]), "+f"(c1[2]), "+f"(c1[3])
                         : "r"(a[ks][0]), "r"(a[ks][1]), "r"(a[ks][2]), "r"(a[ks][3]),
                           "r"(b2), "r"(b3));
        }
        *(__half2*)(ob + (size_t)(m0 + g)     * NPIX + n * 8 + 2 * t)       = __floats2half2_rn(c0[0], c0[1]);
        *(__half2*)(ob + (size_t)(m0 + g + 8) * NPIX + n * 8 + 2 * t)       = __floats2half2_rn(c0[2], c0[3]);
        *(__half2*)(ob + (size_t)(m0 + g)     * NPIX + (n + 1) * 8 + 2 * t) = __floats2half2_rn(c1[0], c1[1]);
        *(__half2*)(ob + (size_t)(m0 + g + 8) * NPIX + (n + 1) * 8 + 2 * t) = __floats2half2_rn(c1[2], c1[3]);
    }
}

// ============================================================
// K2: depthwise 3x3, pad 1. DWROWS=32, fp16 smem (17.4 KB, halo 6%).
// ============================================================
#define DWROWS 32
__global__ __launch_bounds__(256) void k_dw(const float* __restrict__ w) {
    const int tilesY = HH / DWROWS;                 // 8
    const int ytile = blockIdx.x & (tilesY - 1);
    const int ch    = (blockIdx.x / tilesY) % C3;
    const int b     = blockIdx.x / (tilesY * C3);
    const int tid   = threadIdx.x;

    const __half* in  = g_qkv + ((size_t)b * C3 + ch) * NPIX;
    __half*       out = g_dw  + ((size_t)b * C3 + ch) * NPIX;

    __shared__ __half rows[DWROWS + 2][WW];
    const int y0 = ytile * DWROWS;
    for (int i = tid; i < (DWROWS + 2) * (WW / 8); i += 256) {
        int r = i / (WW / 8), c8 = i % (WW / 8);
        int y = y0 - 1 + r;
        if (y >= 0 && y < HH)
            *(uint4*)&rows[r][c8 * 8] = *(const uint4*)(in + y * WW + c8 * 8);
        else {
            uint4 z = {0, 0, 0, 0};
            *(uint4*)&rows[r][c8 * 8] = z;
        }
    }
    __syncthreads();

    const float w00 = w[ch*9+0], w01 = w[ch*9+1], w02 = w[ch*9+2];
    const float w10 = w[ch*9+3], w11 = w[ch*9+4], w12 = w[ch*9+5];
    const float w20 = w[ch*9+6], w21 = w[ch*9+7], w22 = w[ch*9+8];

    const int half = tid >> 7;           // row interleave 0/1
    const int c2   = tid & 127;          // column-pair index
    const int col0 = 2 * c2, col1 = col0 + 1;
    const float lm = (c2 > 0) ? 1.f : 0.f;
    const float rm = (c2 < 127) ? 1.f : 0.f;
    const int xl = max(col0 - 1, 0), xr = min(col1 + 1, WW - 1);

#pragma unroll
    for (int rr = 0; rr < DWROWS / 2; rr++) {
        const int r = 2 * rr + half;
        const __half* r0 = rows[r], *r1 = rows[r + 1], *r2 = rows[r + 2];
        float a0 = __half2float(r0[xl]) * lm, b0 = __half2float(r0[col0]),
              c0v = __half2float(r0[col1]), d0 = __half2float(r0[xr]) * rm;
        float a1 = __half2float(r1[xl]) * lm, b1 = __half2float(r1[col0]),
              c1v = __half2float(r1[col1]), d1 = __half2float(r1[xr]) * rm;
        float a2 = __half2float(r2[xl]) * lm, b2 = __half2float(r2[col0]),
              c2v = __half2float(r2[col1]), d2 = __half2float(r2[xr]) * rm;
        float acc0 = w00*a0 + w01*b0 + w02*c0v + w10*a1 + w11*b1 + w12*c1v + w20*a2 + w21*b2 + w22*c2v;
        float acc1 = w00*b0 + w01*c0v + w02*d0 + w10*b1 + w11*c1v + w12*d1 + w20*b2 + w21*c2v + w22*d2;
        *(__half2*)(out + (y0 + r) * WW + col0) = __floats2half2_rn(acc0, acc1);
    }
}

// ============================================================
// K3: Gram via mma + reg prefetch + fused attn tail (R15/16 WIN).
// ============================================================
__global__ void __launch_bounds__(192) k_gram(const float* __restrict__ proj,
                                              const float* __restrict__ temp) {
    __shared__ __half Qs[C][136];
    __shared__ __half Ks[C][136];
    __shared__ int isLast;
    const int tid  = threadIdx.x;
    const int warp = tid >> 5, lane = tid & 31;
    const int b    = blockIdx.x >> 6;
    const int px0  = (blockIdx.x & 63) << 10;

    const __half* Q = g_dw + (size_t)b * C3 * NPIX;
    const __half* K = Q + (size_t)C * NPIX;

    const int m0     = (warp >> 1) * 16;
    const int n0base = (warp & 1) * 24;
    float c[3][4] = {{0.f}};
    float sq = 0.f;
    const int nch = tid % 96, npart = tid / 96;

    for (int i = tid; i < C * 16; i += 192) {
        int k = i >> 4, q = i & 15;
        *(uint4*)&Qs[k][q * 8] = *(const uint4*)(Q + (size_t)k * NPIX + px0 + q * 8);
        *(uint4*)&Ks[k][q * 8] = *(const uint4*)(K + (size_t)k * NPIX + px0 + q * 8);
    }
    __syncthreads();

#pragma unroll 1
    for (int chk = 0; chk < 8; chk++) {
        uint4 pq[4], pk[4];
        if (chk < 7) {
            const int tb = px0 + (chk + 1) * 128;
#pragma unroll
            for (int j = 0; j < 4; j++) {
                int i = tid + j * 192;
                int k = i >> 4, q = i & 15;
                pq[j] = *(const uint4*)(Q + (size_t)k * NPIX + tb + q * 8);
                pk[j] = *(const uint4*)(K + (size_t)k * NPIX + tb + q * 8);
            }
        }

        {
            const __half2* r2 = (const __half2*)(((nch < C) ? Qs[nch] : Ks[nch - C]) + npart * 64);
#pragma unroll
            for (int j = 0; j < 32; j++) {
                float2 f = __half22float2(r2[j]);
                sq += f.x * f.x + f.y * f.y;
            }
        }

#pragma unroll
        for (int ks = 0; ks < 8; ks++) {
            u32 a0r, a1r, a2r, a3r;
            u32 aaddr = smem_u32(&Qs[m0 + (lane & 15)][ks * 16 + (lane >> 4) * 8]);
            asm volatile("ldmatrix.sync.aligned.m8n8.x4.shared.b16 {%0,%1,%2,%3}, [%4];"
                         : "=r"(a0r), "=r"(a1r), "=r"(a2r), "=r"(a3r) : "r"(aaddr));
#pragma unroll
            for (int j = 0; j < 3; j++) {
                const int n0 = n0base + j * 8;
                u32 b0, b1;
                u32 baddr = smem_u32(&Ks[n0 + (lane & 7)][ks * 16 + ((lane >> 3) & 1) * 8]);
                asm volatile("ldmatrix.sync.aligned.m8n8.x2.shared.b16 {%0,%1}, [%2];"
                             : "=r"(b0), "=r"(b1) : "r"(baddr));
                asm volatile("mma.sync.aligned.m16n8k16.row.col.f32.f16.f16.f32 "
                             "{%0,%1,%2,%3}, {%4,%5,%6,%7}, {%8,%9}, {%0,%1,%2,%3};"
                             : "+f"(c[j][0]), "+f"(c[j][1]), "+f"(c[j][2]), "+f"(c[j][3])
                             : "r"(a0r), "r"(a1r), "r"(a2r), "r"(a3r), "r"(b0), "r"(b1));
            }
        }
        __syncthreads();
        if (chk < 7) {
#pragma unroll
            for (int j = 0; j < 4; j++) {
                int i = tid + j * 192;
                int k = i >> 4, q = i & 15;
                *(uint4*)&Qs[k][q * 8] = pq[j];
                *(uint4*)&Ks[k][q * 8] = pk[j];
            }
            __syncthreads();
        }
    }

    float* gbase = g_small + b * (C * C + 2 * C);
    const int g = lane >> 2, t = lane & 3;
#pragma unroll
    for (int j = 0; j < 3; j++) {
        const int n0 = n0base + j * 8;
        atomicAdd(&gbase[(m0 + g)     * C + n0 + 2 * t],     c[j][0]);
        atomicAdd(&gbase[(m0 + g)     * C + n0 + 2 * t + 1], c[j][1]);
        atomicAdd(&gbase[(m0 + g + 8) * C + n0 + 2 * t],     c[j][2]);
        atomicAdd(&gbase[(m0 + g + 8) * C + n0 + 2 * t + 1], c[j][3]);
    }
    atomicAdd(&gbase[C * C + nch], sq);

    __threadfence();
    if (tid == 0) isLast = (atomicAdd(&g_cnt[b], 1) == 63) ? 1 : 0;
    __syncthreads();
    if (!isLast) return;

    float (*A)[C + 1] = (float(*)[C + 1])Qs;
    float* P  = (float*)Ks;
    float* qn = P + C * C;
    float* kn = qn + C;
    const volatile float* gb = gbase;
    const float T = temp[0];

    for (int i = tid; i < C * C; i += 192) P[i] = proj[i];
    if (tid < C)          qn[tid]     = fmaxf(sqrtf(gb[C * C + tid]), 1e-12f);
    else if (tid < 2 * C) kn[tid - C] = fmaxf(sqrtf(gb[C * C + tid]), 1e-12f);
    __syncthreads();

    for (int i = tid; i < C * C; i += 192) {
        int r = i / C, d = i % C;
        A[r][d] = gb[i] * T / (qn[r] * kn[d]);
    }
    __syncthreads();

    for (int r = warp; r < C; r += 6) {
        float v0 = A[r][lane];
        float v1 = (lane + 32 < C) ? A[r][lane + 32] : -1e30f;
        float mx = fmaxf(v0, v1);
#pragma unroll
        for (int o = 16; o > 0; o >>= 1) mx = fmaxf(mx, __shfl_xor_sync(~0u, mx, o));
        float e0 = expf(v0 - mx);
        float e1 = (lane + 32 < C) ? expf(v1 - mx) : 0.f;
        float s = e0 + e1;
#pragma unroll
        for (int o = 16; o > 0; o >>= 1) s += __shfl_xor_sync(~0u, s, o);
        float inv = 1.f / s;
        A[r][lane] = e0 * inv;
        if (lane + 32 < C) A[r][lane + 32] = e1 * inv;
    }
    __syncthreads();

    float* Mb = g_M + b * C * C;
    for (int oc = warp; oc < C; oc += 6) {
        float acc0 = 0.f, acc1 = 0.f;
#pragma unroll 8
        for (int cc = 0; cc < C; cc++) {
            float p = P[oc * C + cc];
            acc0 += p * A[cc][lane];
            acc1 += p * A[cc][(lane & 15) + 32];
        }
        Mb[oc * C + lane] = acc0;
        if (lane < 16) Mb[oc * C + 32 + lane] = acc1;
    }
}

// ============================================================
// K5: out = M @ V via mma, 256 px/block, x2.trans inner loop.
// ============================================================
__global__ void __launch_bounds__(192) k_out(float* __restrict__ out) {
    __shared__ __half Ms[C][56];
    __shared__ __half Vs[C][264];
    const int tid  = threadIdx.x;
    const int warp = tid >> 5, lane = tid & 31;
    const int b    = blockIdx.x >> 8;            // 256 blocks / batch
    const int px0  = (blockIdx.x & 255) << 8;    // 256 px / block

    const float* Mb = g_M + b * C * C;
    for (int i = tid; i < C * C; i += 192)
        Ms[i / C][i % C] = __float2half_rn(Mb[i]);
    const __half* vb = g_dw + (size_t)b * C3 * NPIX + (size_t)(2 * C) * NPIX + px0;
    for (int i = tid; i < C * 32; i += 192) {
        int k = i >> 5, q = i & 31;
        *(uint4*)&Vs[k][q * 8] = *(const uint4*)(vb + (size_t)k * NPIX + q * 8);
    }
    __syncthreads();

    const int m0 = (warp >> 1) * 16;
    u32 a[3][4];
#pragma unroll
    for (int ks = 0; ks < 3; ks++) {
        u32 addr = smem_u32(&Ms[m0 + (lane & 15)][ks * 16 + (lane >> 4) * 8]);
        asm volatile("ldmatrix.sync.aligned.m8n8.x4.shared.b16 {%0,%1,%2,%3}, [%4];"
                     : "=r"(a[ks][0]), "=r"(a[ks][1]), "=r"(a[ks][2]), "=r"(a[ks][3])
                     : "r"(addr));
    }

    float* ob = out + (size_t)b * C * NPIX + px0;
    const int g = lane >> 2, t = lane & 3;
#pragma unroll 4
    for (int j = 0; j < 16; j++) {
        const int n = (warp & 1) * 16 + j;
        float c0 = 0.f, c1 = 0.f, c2 = 0.f, c3 = 0.f;
#pragma unroll
        for (int ks = 0; ks < 3; ks++) {
            u32 b0, b1;
            u32 baddr = smem_u32(&Vs[ks * 16 + (lane & 15)][n * 8]);
            asm volatile("ldmatrix.sync.aligned.m8n8.x2.trans.shared.b16 {%0,%1}, [%2];"
                         : "=r"(b0), "=r"(b1) : "r"(baddr));
            asm volatile("mma.sync.aligned.m16n8k16.row.col.f32.f16.f16.f32 "
                         "{%0,%1,%2,%3}, {%4,%5,%6,%7}, {%8,%9}, {%0,%1,%2,%3};"
                         : "+f"(c0), "+f"(c1), "+f"(c2), "+f"(c3)
                         : "r"(a[ks][0]), "r"(a[ks][1]), "r"(a[ks][2]), "r"(a[ks][3]),
                           "r"(b0), "r"(b1));
        }
        *(float2*)(ob + (size_t)(m0 + g)     * NPIX + n * 8 + 2 * t) = make_float2(c0, c1);
        *(float2*)(ob + (size_t)(m0 + g + 8) * NPIX + n * 8 + 2 * t) = make_float2(c2, c3);
    }
}

// ============================================================
extern "C" void kernel_launch(void* const* d_in, const int* in_sizes, int n_in,
                              void* d_out, int out_size) {
    const float* x      = (const float*)d_in[0];
    const float* qkv_w  = (const float*)d_in[1];
    const float* dw_w   = (const float*)d_in[2];
    const float* proj_w = (const float*)d_in[3];
    const float* temp   = (const float*)d_in[4];

    void* smallp = nullptr;
    cudaGetSymbolAddress(&smallp, g_small);
    cudaMemsetAsync(smallp, 0, sizeof(float) * Bc * (C * C + 2 * C));
    void* cntp = nullptr;
    cudaGetSymbolAddress(&cntp, g_cnt);
    cudaMemsetAsync(cntp, 0, sizeof(int) * Bc);

    k_qkv <<<Bc * 256,                288>>>(x, qkv_w);
    k_dw  <<<Bc * C3 * (HH / DWROWS), 256>>>(dw_w);
    k_gram<<<Bc * 64,                 192>>>(proj_w, temp);
    k_out <<<Bc * 256,                192>>>((float*)d_out);
}